// round 4
// baseline (speedup 1.0000x reference)
#include <cuda_runtime.h>
#include <cstdint>

#define N_NODES 100000
#define NFEAT   256
#define NHID    128
#define NHID2   64

// Scratch (no cudaMalloc allowed)
__device__ float g_H0[(size_t)N_NODES * NHID];    // x @ W1
__device__ float g_H1[(size_t)N_NODES * NHID];    // relu(spmm(A,H0)+b1)
__device__ float g_H2[(size_t)N_NODES * NHID2];   // H1 @ W2
__device__ int   g_rowptr[N_NODES + 1];

// ---------------------------------------------------------------------------
// row_ptr from sorted COO rows: rp[i] = lower_bound(rows, i)
// ---------------------------------------------------------------------------
__global__ void rowptr_kernel(const int* __restrict__ rows, int E,
                              int* __restrict__ rp) {
    int i = blockIdx.x * blockDim.x + threadIdx.x;
    if (i > N_NODES) return;
    int lo = 0, hi = E;
    while (lo < hi) {
        int mid = (lo + hi) >> 1;
        if (rows[mid] < i) lo = mid + 1; else hi = mid;
    }
    rp[i] = lo;
}

// ---------------------------------------------------------------------------
// TF32 helpers (3xTF32 split for ~fp32 accuracy on tensor cores)
// ---------------------------------------------------------------------------
__device__ __forceinline__ uint2 split2_tf32(float x) {
    uint32_t hi, lo;
    asm("cvt.rna.tf32.f32 %0, %1;" : "=r"(hi) : "f"(x));
    float r = x - __uint_as_float(hi);
    asm("cvt.rna.tf32.f32 %0, %1;" : "=r"(lo) : "f"(r));
    return make_uint2(hi, lo);
}

__device__ __forceinline__ void mma_tf32(float* d, const uint32_t* a,
                                         const uint32_t* b) {
    asm("mma.sync.aligned.m16n8k8.row.col.f32.tf32.tf32.f32 "
        "{%0,%1,%2,%3},{%4,%5,%6,%7},{%8,%9},{%0,%1,%2,%3};"
        : "+f"(d[0]), "+f"(d[1]), "+f"(d[2]), "+f"(d[3])
        : "r"(a[0]), "r"(a[1]), "r"(a[2]), "r"(a[3]), "r"(b[0]), "r"(b[1]));
}

// ---------------------------------------------------------------------------
// Tensor-core GEMM: C[M,N] = A[M,K] @ B[K,N], fp32 in/out, 3xTF32 internally.
// tf32 hi/lo split is precomputed at tile-staging time and stored interleaved
// as uint2 in smem, so the mainloop is pure LDS.64 + HMMA.
// Block 256 thr, tile BM=128 x BN=64, BK=32. Warps: 4(m) x 2(n), warp=32x32.
// ---------------------------------------------------------------------------
#define GBM 128
#define GBN 64
#define GBK 32
#define APITCH 36   // uint2 elems per A row (conflict-free for .64 frag loads)
#define BPITCH 68   // uint2 elems per B row
#define GEMM_SMEM ((GBM * APITCH + GBK * BPITCH) * (int)sizeof(uint2))

__global__ __launch_bounds__(256) void gemm_tf32_kernel(
    const float* __restrict__ A, const float* __restrict__ B,
    float* __restrict__ C, int M, int N, int K) {
    extern __shared__ uint2 sm[];
    uint2* As2 = sm;                       // [GBM][APITCH]
    uint2* Bs2 = sm + GBM * APITCH;        // [GBK][BPITCH]

    const int tid  = threadIdx.x;
    const int wid  = tid >> 5, lane = tid & 31;
    const int g    = lane >> 2, tig = lane & 3;
    const int warp_m = wid >> 1, warp_n = wid & 1;
    const int mBase = blockIdx.x * GBM;
    const int nBase = blockIdx.y * GBN;
    const int KT = K / GBK;

    float acc[2][4][4];
#pragma unroll
    for (int mi = 0; mi < 2; mi++)
#pragma unroll
        for (int ni = 0; ni < 4; ni++)
#pragma unroll
            for (int r = 0; r < 4; r++) acc[mi][ni][r] = 0.f;

    float4 aReg[4], bReg[2];

    auto loadTile = [&](int kt) {
#pragma unroll
        for (int i = 0; i < 4; i++) {
            int idx = tid + i * 256;
            int row = idx >> 3, kc = (idx & 7) << 2;
            int grow = mBase + row;
            float4 v = make_float4(0.f, 0.f, 0.f, 0.f);
            if (grow < M)
                v = *reinterpret_cast<const float4*>(
                        &A[(size_t)grow * K + kt * GBK + kc]);
            aReg[i] = v;
        }
#pragma unroll
        for (int i = 0; i < 2; i++) {
            int idx = tid + i * 256;
            int kr = idx >> 4, nc = (idx & 15) << 2;
            bReg[i] = *reinterpret_cast<const float4*>(
                          &B[(size_t)(kt * GBK + kr) * N + nBase + nc]);
        }
    };
    auto stageTile = [&]() {
#pragma unroll
        for (int i = 0; i < 4; i++) {
            int idx = tid + i * 256;
            int row = idx >> 3, kc = (idx & 7) << 2;
            float4 v = aReg[i];
            uint2 s0 = split2_tf32(v.x), s1 = split2_tf32(v.y);
            uint2 s2 = split2_tf32(v.z), s3 = split2_tf32(v.w);
            *reinterpret_cast<uint4*>(&As2[row * APITCH + kc]) =
                make_uint4(s0.x, s0.y, s1.x, s1.y);
            *reinterpret_cast<uint4*>(&As2[row * APITCH + kc + 2]) =
                make_uint4(s2.x, s2.y, s3.x, s3.y);
        }
#pragma unroll
        for (int i = 0; i < 2; i++) {
            int idx = tid + i * 256;
            int kr = idx >> 4, nc = (idx & 15) << 2;
            float4 v = bReg[i];
            uint2 s0 = split2_tf32(v.x), s1 = split2_tf32(v.y);
            uint2 s2 = split2_tf32(v.z), s3 = split2_tf32(v.w);
            *reinterpret_cast<uint4*>(&Bs2[kr * BPITCH + nc]) =
                make_uint4(s0.x, s0.y, s1.x, s1.y);
            *reinterpret_cast<uint4*>(&Bs2[kr * BPITCH + nc + 2]) =
                make_uint4(s2.x, s2.y, s3.x, s3.y);
        }
    };

    loadTile(0);
    stageTile();
    __syncthreads();

    for (int kt = 0; kt < KT; kt++) {
        if (kt + 1 < KT) loadTile(kt + 1);

#pragma unroll
        for (int ka = 0; ka < 4; ka++) {
            uint32_t ah[2][4], al[2][4], bh[4][2], bl[4][2];
#pragma unroll
            for (int mi = 0; mi < 2; mi++) {
                int row = warp_m * 32 + mi * 16 + g;
                int k0 = ka * 8 + tig;
                uint2 t;
                t = As2[row * APITCH + k0];           ah[mi][0] = t.x; al[mi][0] = t.y;
                t = As2[(row + 8) * APITCH + k0];     ah[mi][1] = t.x; al[mi][1] = t.y;
                t = As2[row * APITCH + k0 + 4];       ah[mi][2] = t.x; al[mi][2] = t.y;
                t = As2[(row + 8) * APITCH + k0 + 4]; ah[mi][3] = t.x; al[mi][3] = t.y;
            }
#pragma unroll
            for (int ni = 0; ni < 4; ni++) {
                int col = warp_n * 32 + ni * 8 + g;
                uint2 t;
                t = Bs2[(ka * 8 + tig) * BPITCH + col];     bh[ni][0] = t.x; bl[ni][0] = t.y;
                t = Bs2[(ka * 8 + tig + 4) * BPITCH + col]; bh[ni][1] = t.x; bl[ni][1] = t.y;
            }
#pragma unroll
            for (int mi = 0; mi < 2; mi++)
#pragma unroll
                for (int ni = 0; ni < 4; ni++) {
                    mma_tf32(acc[mi][ni], ah[mi], bh[ni]);
                    mma_tf32(acc[mi][ni], ah[mi], bl[ni]);
                    mma_tf32(acc[mi][ni], al[mi], bh[ni]);
                }
        }
        __syncthreads();
        if (kt + 1 < KT) {
            stageTile();
            __syncthreads();
        }
    }

    // store
#pragma unroll
    for (int mi = 0; mi < 2; mi++) {
        int row = mBase + warp_m * 32 + mi * 16 + g;
#pragma unroll
        for (int ni = 0; ni < 4; ni++) {
            int col = nBase + warp_n * 32 + ni * 8 + 2 * tig;
            if (row < M)
                *reinterpret_cast<float2*>(&C[(size_t)row * N + col]) =
                    make_float2(acc[mi][ni][0], acc[mi][ni][1]);
            if (row + 8 < M)
                *reinterpret_cast<float2*>(&C[(size_t)(row + 8) * N + col]) =
                    make_float2(acc[mi][ni][2], acc[mi][ni][3]);
        }
    }
}

// ---------------------------------------------------------------------------
// CSR SpMM, warp per node, no atomics. Edge (col,val) pairs loaded one per
// lane (2 coalesced wavefronts / 32 edges) and broadcast via shfl.
// Fused bias+ReLU on store.
// ---------------------------------------------------------------------------
#define FULLMASK 0xFFFFFFFFu

__global__ __launch_bounds__(256) void spmm_csr_f128(
    const float* __restrict__ vals, const int* __restrict__ cols,
    const int* __restrict__ rp, const float4* __restrict__ H4,
    const float4* __restrict__ bias4, float4* __restrict__ out4) {
    int node = blockIdx.x * (blockDim.x >> 5) + (threadIdx.x >> 5);
    int lane = threadIdx.x & 31;
    if (node >= N_NODES) return;
    int s = rp[node], e = rp[node + 1];

    float4 acc = make_float4(0.f, 0.f, 0.f, 0.f);
    for (int base = s; base < e; base += 32) {
        int m = e - base;
        if (m > 32) m = 32;
        int c = 0; float v = 0.f;
        if (base + lane < e) {
            c = __ldcs(&cols[base + lane]);
            v = __ldcs(&vals[base + lane]);
        }
        int j = 0;
        for (; j + 4 <= m; j += 4) {
            int c0 = __shfl_sync(FULLMASK, c, j);
            int c1 = __shfl_sync(FULLMASK, c, j + 1);
            int c2 = __shfl_sync(FULLMASK, c, j + 2);
            int c3 = __shfl_sync(FULLMASK, c, j + 3);
            float v0 = __shfl_sync(FULLMASK, v, j);
            float v1 = __shfl_sync(FULLMASK, v, j + 1);
            float v2 = __shfl_sync(FULLMASK, v, j + 2);
            float v3 = __shfl_sync(FULLMASK, v, j + 3);
            float4 h0 = __ldg(&H4[(size_t)c0 * 32 + lane]);
            float4 h1 = __ldg(&H4[(size_t)c1 * 32 + lane]);
            float4 h2 = __ldg(&H4[(size_t)c2 * 32 + lane]);
            float4 h3 = __ldg(&H4[(size_t)c3 * 32 + lane]);
            acc.x = fmaf(v0, h0.x, acc.x); acc.y = fmaf(v0, h0.y, acc.y);
            acc.z = fmaf(v0, h0.z, acc.z); acc.w = fmaf(v0, h0.w, acc.w);
            acc.x = fmaf(v1, h1.x, acc.x); acc.y = fmaf(v1, h1.y, acc.y);
            acc.z = fmaf(v1, h1.z, acc.z); acc.w = fmaf(v1, h1.w, acc.w);
            acc.x = fmaf(v2, h2.x, acc.x); acc.y = fmaf(v2, h2.y, acc.y);
            acc.z = fmaf(v2, h2.z, acc.z); acc.w = fmaf(v2, h2.w, acc.w);
            acc.x = fmaf(v3, h3.x, acc.x); acc.y = fmaf(v3, h3.y, acc.y);
            acc.z = fmaf(v3, h3.z, acc.z); acc.w = fmaf(v3, h3.w, acc.w);
        }
        for (; j < m; j++) {
            int   cj = __shfl_sync(FULLMASK, c, j);
            float vj = __shfl_sync(FULLMASK, v, j);
            float4 h = __ldg(&H4[(size_t)cj * 32 + lane]);
            acc.x = fmaf(vj, h.x, acc.x); acc.y = fmaf(vj, h.y, acc.y);
            acc.z = fmaf(vj, h.z, acc.z); acc.w = fmaf(vj, h.w, acc.w);
        }
    }
    float4 b = bias4[lane];
    acc.x = fmaxf(acc.x + b.x, 0.f);
    acc.y = fmaxf(acc.y + b.y, 0.f);
    acc.z = fmaxf(acc.z + b.z, 0.f);
    acc.w = fmaxf(acc.w + b.w, 0.f);
    out4[(size_t)node * 32 + lane] = acc;
}

__global__ __launch_bounds__(256) void spmm_csr_f64(
    const float* __restrict__ vals, const int* __restrict__ cols,
    const int* __restrict__ rp, const float2* __restrict__ H2,
    const float2* __restrict__ bias2, float2* __restrict__ out2) {
    int node = blockIdx.x * (blockDim.x >> 5) + (threadIdx.x >> 5);
    int lane = threadIdx.x & 31;
    if (node >= N_NODES) return;
    int s = rp[node], e = rp[node + 1];

    float2 acc = make_float2(0.f, 0.f);
    for (int base = s; base < e; base += 32) {
        int m = e - base;
        if (m > 32) m = 32;
        int c = 0; float v = 0.f;
        if (base + lane < e) {
            c = __ldcs(&cols[base + lane]);
            v = __ldcs(&vals[base + lane]);
        }
        int j = 0;
        for (; j + 4 <= m; j += 4) {
            int c0 = __shfl_sync(FULLMASK, c, j);
            int c1 = __shfl_sync(FULLMASK, c, j + 1);
            int c2 = __shfl_sync(FULLMASK, c, j + 2);
            int c3 = __shfl_sync(FULLMASK, c, j + 3);
            float v0 = __shfl_sync(FULLMASK, v, j);
            float v1 = __shfl_sync(FULLMASK, v, j + 1);
            float v2 = __shfl_sync(FULLMASK, v, j + 2);
            float v3 = __shfl_sync(FULLMASK, v, j + 3);
            float2 h0 = __ldg(&H2[(size_t)c0 * 32 + lane]);
            float2 h1 = __ldg(&H2[(size_t)c1 * 32 + lane]);
            float2 h2 = __ldg(&H2[(size_t)c2 * 32 + lane]);
            float2 h3 = __ldg(&H2[(size_t)c3 * 32 + lane]);
            acc.x = fmaf(v0, h0.x, acc.x); acc.y = fmaf(v0, h0.y, acc.y);
            acc.x = fmaf(v1, h1.x, acc.x); acc.y = fmaf(v1, h1.y, acc.y);
            acc.x = fmaf(v2, h2.x, acc.x); acc.y = fmaf(v2, h2.y, acc.y);
            acc.x = fmaf(v3, h3.x, acc.x); acc.y = fmaf(v3, h3.y, acc.y);
        }
        for (; j < m; j++) {
            int   cj = __shfl_sync(FULLMASK, c, j);
            float vj = __shfl_sync(FULLMASK, v, j);
            float2 h = __ldg(&H2[(size_t)cj * 32 + lane]);
            acc.x = fmaf(vj, h.x, acc.x); acc.y = fmaf(vj, h.y, acc.y);
        }
    }
    float2 b = bias2[lane];
    acc.x = fmaxf(acc.x + b.x, 0.f);
    acc.y = fmaxf(acc.y + b.y, 0.f);
    out2[(size_t)node * 32 + lane] = acc;
}

// ---------------------------------------------------------------------------
extern "C" void kernel_launch(void* const* d_in, const int* in_sizes, int n_in,
                              void* d_out, int out_size) {
    const float* x     = (const float*)d_in[0];
    const float* W1    = (const float*)d_in[1];
    const float* b1    = (const float*)d_in[2];
    const float* W2    = (const float*)d_in[3];
    const float* b2    = (const float*)d_in[4];
    const float* evals = (const float*)d_in[5];
    const int*   erows = (const int*)d_in[6];
    const int*   ecols = (const int*)d_in[7];
    float*       out   = (float*)d_out;

    const int E = in_sizes[5];

    void *pH0, *pH1, *pH2, *pRP;
    cudaGetSymbolAddress(&pH0, g_H0);
    cudaGetSymbolAddress(&pH1, g_H1);
    cudaGetSymbolAddress(&pH2, g_H2);
    cudaGetSymbolAddress(&pRP, g_rowptr);
    float* H0 = (float*)pH0;
    float* H1 = (float*)pH1;
    float* H2 = (float*)pH2;
    int*   rp = (int*)pRP;

    cudaFuncSetAttribute(gemm_tf32_kernel,
                         cudaFuncAttributeMaxDynamicSharedMemorySize, GEMM_SMEM);

    // row_ptr from sorted rows
    rowptr_kernel<<<(N_NODES + 1 + 255) / 256, 256>>>(erows, E, rp);

    // GEMM1: H0 = x @ W1   (M=100000, N=128, K=256)
    {
        dim3 grid((N_NODES + GBM - 1) / GBM, NHID / GBN);
        gemm_tf32_kernel<<<grid, 256, GEMM_SMEM>>>(x, W1, H0, N_NODES, NHID, NFEAT);
    }

    // SpMM1: H1 = relu(A @ H0 + b1)
    {
        int warps_per_block = 8;
        int grid = (N_NODES + warps_per_block - 1) / warps_per_block;
        spmm_csr_f128<<<grid, 256>>>(evals, ecols, rp, (const float4*)H0,
                                     (const float4*)b1, (float4*)H1);
    }

    // GEMM2: H2 = H1 @ W2   (M=100000, N=64, K=128)
    {
        dim3 grid((N_NODES + GBM - 1) / GBM, NHID2 / GBN);
        gemm_tf32_kernel<<<grid, 256, GEMM_SMEM>>>(H1, W2, H2, N_NODES, NHID2, NHID);
    }

    // SpMM2: out = relu(A @ H2 + b2)
    {
        int warps_per_block = 8;
        int grid = (N_NODES + warps_per_block - 1) / warps_per_block;
        spmm_csr_f64<<<grid, 256>>>(evals, ecols, rp, (const float2*)H2,
                                    (const float2*)b2, (float2*)out);
    }
}

// round 5
// speedup vs baseline: 1.0463x; 1.0463x over previous
#include <cuda_runtime.h>
#include <cstdint>

#define N_NODES 100000
#define NFEAT   256
#define NHID    128
#define NHID2   64

// Scratch (no cudaMalloc allowed)
__device__ float g_H0[(size_t)N_NODES * NHID];    // x @ W1
__device__ float g_H1[(size_t)N_NODES * NHID];    // relu(spmm(A,H0)+b1)
__device__ float g_H2[(size_t)N_NODES * NHID2];   // H1 @ W2
__device__ int   g_rowptr[N_NODES + 1];

// ---------------------------------------------------------------------------
// row_ptr from sorted COO rows: rp[i] = lower_bound(rows, i)
// ---------------------------------------------------------------------------
__global__ void rowptr_kernel(const int* __restrict__ rows, int E,
                              int* __restrict__ rp) {
    int i = blockIdx.x * blockDim.x + threadIdx.x;
    if (i > N_NODES) return;
    int lo = 0, hi = E;
    while (lo < hi) {
        int mid = (lo + hi) >> 1;
        if (rows[mid] < i) lo = mid + 1; else hi = mid;
    }
    rp[i] = lo;
}

// ---------------------------------------------------------------------------
// TF32 helpers (3xTF32 split for ~fp32 accuracy on tensor cores)
// ---------------------------------------------------------------------------
__device__ __forceinline__ void split_tf32(float x, uint32_t& hi, uint32_t& lo) {
    asm("cvt.rna.tf32.f32 %0, %1;" : "=r"(hi) : "f"(x));
    float hif = __uint_as_float(hi);
    float lof = x - hif;
    asm("cvt.rna.tf32.f32 %0, %1;" : "=r"(lo) : "f"(lof));
}

__device__ __forceinline__ void mma_tf32(float* d, const uint32_t* a,
                                         const uint32_t* b) {
    asm("mma.sync.aligned.m16n8k8.row.col.f32.tf32.tf32.f32 "
        "{%0,%1,%2,%3},{%4,%5,%6,%7},{%8,%9},{%0,%1,%2,%3};"
        : "+f"(d[0]), "+f"(d[1]), "+f"(d[2]), "+f"(d[3])
        : "r"(a[0]), "r"(a[1]), "r"(a[2]), "r"(a[3]), "r"(b[0]), "r"(b[1]));
}

// ---------------------------------------------------------------------------
// Tensor-core GEMM (exact R3 version, measured 43us for M=100k,N=128,K=256).
// Block 256 thr, tile BM=128 x BN=64, BK=32. Warps: 4(m) x 2(n), warp=32x32.
// ---------------------------------------------------------------------------
#define GBM 128
#define GBN 64
#define GBK 32

__global__ __launch_bounds__(256) void gemm_tf32_kernel(
    const float* __restrict__ A, const float* __restrict__ B,
    float* __restrict__ C, int M, int N, int K) {
    __shared__ float As[GBM][GBK + 4];
    __shared__ float Bs[GBK][GBN + 4];

    const int tid  = threadIdx.x;
    const int wid  = tid >> 5, lane = tid & 31;
    const int g    = lane >> 2, tig = lane & 3;
    const int warp_m = wid >> 1, warp_n = wid & 1;
    const int mBase = blockIdx.x * GBM;
    const int nBase = blockIdx.y * GBN;
    const int KT = K / GBK;

    float acc[2][4][4];
#pragma unroll
    for (int mi = 0; mi < 2; mi++)
#pragma unroll
        for (int ni = 0; ni < 4; ni++)
#pragma unroll
            for (int r = 0; r < 4; r++) acc[mi][ni][r] = 0.f;

    float4 aReg[4], bReg[2];

    auto loadTile = [&](int kt) {
#pragma unroll
        for (int i = 0; i < 4; i++) {
            int idx = tid + i * 256;
            int row = idx >> 3, kc = (idx & 7) << 2;
            int grow = mBase + row;
            float4 v = make_float4(0.f, 0.f, 0.f, 0.f);
            if (grow < M)
                v = *reinterpret_cast<const float4*>(
                        &A[(size_t)grow * K + kt * GBK + kc]);
            aReg[i] = v;
        }
#pragma unroll
        for (int i = 0; i < 2; i++) {
            int idx = tid + i * 256;
            int kr = idx >> 4, nc = (idx & 15) << 2;
            bReg[i] = *reinterpret_cast<const float4*>(
                          &B[(size_t)(kt * GBK + kr) * N + nBase + nc]);
        }
    };
    auto stageTile = [&]() {
#pragma unroll
        for (int i = 0; i < 4; i++) {
            int idx = tid + i * 256;
            int row = idx >> 3, kc = (idx & 7) << 2;
            *reinterpret_cast<float4*>(&As[row][kc]) = aReg[i];
        }
#pragma unroll
        for (int i = 0; i < 2; i++) {
            int idx = tid + i * 256;
            int kr = idx >> 4, nc = (idx & 15) << 2;
            *reinterpret_cast<float4*>(&Bs[kr][nc]) = bReg[i];
        }
    };

    loadTile(0);
    stageTile();
    __syncthreads();

    for (int kt = 0; kt < KT; kt++) {
        if (kt + 1 < KT) loadTile(kt + 1);

#pragma unroll
        for (int ka = 0; ka < 4; ka++) {
            uint32_t ah[2][4], al[2][4], bh[4][2], bl[4][2];
#pragma unroll
            for (int mi = 0; mi < 2; mi++) {
                int row = warp_m * 32 + mi * 16 + g;
                int k0 = ka * 8 + tig;
                split_tf32(As[row][k0],       ah[mi][0], al[mi][0]);
                split_tf32(As[row + 8][k0],   ah[mi][1], al[mi][1]);
                split_tf32(As[row][k0 + 4],   ah[mi][2], al[mi][2]);
                split_tf32(As[row + 8][k0+4], ah[mi][3], al[mi][3]);
            }
#pragma unroll
            for (int ni = 0; ni < 4; ni++) {
                int col = warp_n * 32 + ni * 8 + g;
                split_tf32(Bs[ka * 8 + tig][col],     bh[ni][0], bl[ni][0]);
                split_tf32(Bs[ka * 8 + tig + 4][col], bh[ni][1], bl[ni][1]);
            }
#pragma unroll
            for (int mi = 0; mi < 2; mi++)
#pragma unroll
                for (int ni = 0; ni < 4; ni++) {
                    mma_tf32(acc[mi][ni], ah[mi], bh[ni]);
                    mma_tf32(acc[mi][ni], ah[mi], bl[ni]);
                    mma_tf32(acc[mi][ni], al[mi], bh[ni]);
                }
        }
        __syncthreads();
        if (kt + 1 < KT) {
            stageTile();
            __syncthreads();
        }
    }

    // store
#pragma unroll
    for (int mi = 0; mi < 2; mi++) {
        int row = mBase + warp_m * 32 + mi * 16 + g;
#pragma unroll
        for (int ni = 0; ni < 4; ni++) {
            int col = nBase + warp_n * 32 + ni * 8 + 2 * tig;
            if (row < M)
                *reinterpret_cast<float2*>(&C[(size_t)row * N + col]) =
                    make_float2(acc[mi][ni][0], acc[mi][ni][1]);
            if (row + 8 < M)
                *reinterpret_cast<float2*>(&C[(size_t)(row + 8) * N + col]) =
                    make_float2(acc[mi][ni][2], acc[mi][ni][3]);
        }
    }
}

// ---------------------------------------------------------------------------
// CSR SpMM, warp per node, 64 features (float2/lane) per pass.
// ROWF2 = row length of H and out in float2 units. COFF = column offset
// (float2 units) of this pass. Column-blocking keeps the gather working set
// L2-resident (~64MB/pass vs ~115MB unsplit).
// Edge metadata read via aligned int4/float4 (0.5 wavefronts/edge).
// Fused bias+ReLU on store.
// ---------------------------------------------------------------------------
template <int ROWF2>
__global__ __launch_bounds__(256) void spmm_csr_pass(
    const float* __restrict__ vals, const int* __restrict__ cols,
    const int* __restrict__ rp, const float2* __restrict__ H,
    const float2* __restrict__ bias2, float2* __restrict__ out,
    int coff) {
    int node = blockIdx.x * 8 + (threadIdx.x >> 5);
    int lane = threadIdx.x & 31;
    if (node >= N_NODES) return;
    int s = rp[node], e = rp[node + 1];

    const float2* __restrict__ Hc = H + coff + lane;

    float2 acc = make_float2(0.f, 0.f);
    int i = s;
    // head: to 16B alignment of cols
    for (; i < e && (i & 3); i++) {
        int   c = __ldg(&cols[i]);
        float v = __ldg(&vals[i]);
        float2 h = __ldg(&Hc[(size_t)c * ROWF2]);
        acc.x = fmaf(v, h.x, acc.x); acc.y = fmaf(v, h.y, acc.y);
    }
    // aligned body: 4 edges per int4/float4
    for (; i + 4 <= e; i += 4) {
        int4   c4 = __ldg(reinterpret_cast<const int4*>(&cols[i]));
        float4 v4 = __ldg(reinterpret_cast<const float4*>(&vals[i]));
        float2 h0 = __ldg(&Hc[(size_t)c4.x * ROWF2]);
        float2 h1 = __ldg(&Hc[(size_t)c4.y * ROWF2]);
        float2 h2 = __ldg(&Hc[(size_t)c4.z * ROWF2]);
        float2 h3 = __ldg(&Hc[(size_t)c4.w * ROWF2]);
        acc.x = fmaf(v4.x, h0.x, acc.x); acc.y = fmaf(v4.x, h0.y, acc.y);
        acc.x = fmaf(v4.y, h1.x, acc.x); acc.y = fmaf(v4.y, h1.y, acc.y);
        acc.x = fmaf(v4.z, h2.x, acc.x); acc.y = fmaf(v4.z, h2.y, acc.y);
        acc.x = fmaf(v4.w, h3.x, acc.x); acc.y = fmaf(v4.w, h3.y, acc.y);
    }
    // tail
    for (; i < e; i++) {
        int   c = __ldg(&cols[i]);
        float v = __ldg(&vals[i]);
        float2 h = __ldg(&Hc[(size_t)c * ROWF2]);
        acc.x = fmaf(v, h.x, acc.x); acc.y = fmaf(v, h.y, acc.y);
    }

    float2 b = bias2[coff + lane];
    acc.x = fmaxf(acc.x + b.x, 0.f);
    acc.y = fmaxf(acc.y + b.y, 0.f);
    out[(size_t)node * ROWF2 + coff + lane] = acc;
}

// ---------------------------------------------------------------------------
extern "C" void kernel_launch(void* const* d_in, const int* in_sizes, int n_in,
                              void* d_out, int out_size) {
    const float* x     = (const float*)d_in[0];
    const float* W1    = (const float*)d_in[1];
    const float* b1    = (const float*)d_in[2];
    const float* W2    = (const float*)d_in[3];
    const float* b2    = (const float*)d_in[4];
    const float* evals = (const float*)d_in[5];
    const int*   erows = (const int*)d_in[6];
    const int*   ecols = (const int*)d_in[7];
    float*       out   = (float*)d_out;

    const int E = in_sizes[5];

    void *pH0, *pH1, *pH2, *pRP;
    cudaGetSymbolAddress(&pH0, g_H0);
    cudaGetSymbolAddress(&pH1, g_H1);
    cudaGetSymbolAddress(&pH2, g_H2);
    cudaGetSymbolAddress(&pRP, g_rowptr);
    float* H0 = (float*)pH0;
    float* H1 = (float*)pH1;
    float* H2 = (float*)pH2;
    int*   rp = (int*)pRP;

    const int SPMM_GRID = (N_NODES + 7) / 8;

    // row_ptr from sorted rows
    rowptr_kernel<<<(N_NODES + 1 + 255) / 256, 256>>>(erows, E, rp);

    // GEMM1: H0 = x @ W1   (M=100000, N=128, K=256)
    {
        dim3 grid((N_NODES + GBM - 1) / GBM, NHID / GBN);
        gemm_tf32_kernel<<<grid, 256>>>(x, W1, H0, N_NODES, NHID, NFEAT);
    }

    // SpMM1: H1 = relu(A @ H0 + b1), two column-blocked passes of 64 features
    spmm_csr_pass<64><<<SPMM_GRID, 256>>>(evals, ecols, rp, (const float2*)H0,
                                          (const float2*)b1, (float2*)H1, 0);
    spmm_csr_pass<64><<<SPMM_GRID, 256>>>(evals, ecols, rp, (const float2*)H0,
                                          (const float2*)b1, (float2*)H1, 32);

    // GEMM2: H2 = H1 @ W2   (M=100000, N=64, K=128)
    {
        dim3 grid((N_NODES + GBM - 1) / GBM, NHID2 / GBN);
        gemm_tf32_kernel<<<grid, 256>>>(H1, W2, H2, N_NODES, NHID2, NHID);
    }

    // SpMM2: out = relu(A @ H2 + b2), single pass (working set fits L2)
    spmm_csr_pass<32><<<SPMM_GRID, 256>>>(evals, ecols, rp, (const float2*)H2,
                                          (const float2*)b2, (float2*)out, 0);
}

// round 6
// speedup vs baseline: 1.2200x; 1.1661x over previous
#include <cuda_runtime.h>
#include <cuda_fp16.h>
#include <cstdint>

#define N_NODES 100000
#define NFEAT   256
#define NHID    128
#define NHID2   64

// Scratch (no cudaMalloc allowed). H0/H2 stored as fp16 (halves gather bytes).
__device__ __half g_H0h[(size_t)N_NODES * NHID];   // fp16(x @ W1)
__device__ float  g_H1[(size_t)N_NODES * NHID];    // relu(spmm(A,H0)+b1)  fp32
__device__ __half g_H2h[(size_t)N_NODES * NHID2];  // fp16(H1 @ W2)
__device__ int    g_rowptr[N_NODES + 1];

// ---------------------------------------------------------------------------
// row_ptr from sorted COO rows: rp[i] = lower_bound(rows, i)
// ---------------------------------------------------------------------------
__global__ void rowptr_kernel(const int* __restrict__ rows, int E,
                              int* __restrict__ rp) {
    int i = blockIdx.x * blockDim.x + threadIdx.x;
    if (i > N_NODES) return;
    int lo = 0, hi = E;
    while (lo < hi) {
        int mid = (lo + hi) >> 1;
        if (rows[mid] < i) lo = mid + 1; else hi = mid;
    }
    rp[i] = lo;
}

// ---------------------------------------------------------------------------
// TF32 helpers (3xTF32 split for ~fp32 accuracy on tensor cores)
// ---------------------------------------------------------------------------
__device__ __forceinline__ void split_tf32(float x, uint32_t& hi, uint32_t& lo) {
    asm("cvt.rna.tf32.f32 %0, %1;" : "=r"(hi) : "f"(x));
    float hif = __uint_as_float(hi);
    float lof = x - hif;
    asm("cvt.rna.tf32.f32 %0, %1;" : "=r"(lo) : "f"(lof));
}

__device__ __forceinline__ void mma_tf32(float* d, const uint32_t* a,
                                         const uint32_t* b) {
    asm("mma.sync.aligned.m16n8k8.row.col.f32.tf32.tf32.f32 "
        "{%0,%1,%2,%3},{%4,%5,%6,%7},{%8,%9},{%0,%1,%2,%3};"
        : "+f"(d[0]), "+f"(d[1]), "+f"(d[2]), "+f"(d[3])
        : "r"(a[0]), "r"(a[1]), "r"(a[2]), "r"(a[3]), "r"(b[0]), "r"(b[1]));
}

// ---------------------------------------------------------------------------
// Tensor-core GEMM (R3 mainloop, measured 43us for M=100k,N=128,K=256).
// HALF_OUT: epilogue converts to fp16 and stores __half2 (for SpMM gathers).
// Block 256 thr, tile BM=128 x BN=64, BK=32. Warps: 4(m) x 2(n), warp=32x32.
// ---------------------------------------------------------------------------
#define GBM 128
#define GBN 64
#define GBK 32

template <bool HALF_OUT>
__global__ __launch_bounds__(256) void gemm_tf32_kernel(
    const float* __restrict__ A, const float* __restrict__ B,
    void* __restrict__ Cv, int M, int N, int K) {
    __shared__ float As[GBM][GBK + 4];
    __shared__ float Bs[GBK][GBN + 4];

    const int tid  = threadIdx.x;
    const int wid  = tid >> 5, lane = tid & 31;
    const int g    = lane >> 2, tig = lane & 3;
    const int warp_m = wid >> 1, warp_n = wid & 1;
    const int mBase = blockIdx.x * GBM;
    const int nBase = blockIdx.y * GBN;
    const int KT = K / GBK;

    float acc[2][4][4];
#pragma unroll
    for (int mi = 0; mi < 2; mi++)
#pragma unroll
        for (int ni = 0; ni < 4; ni++)
#pragma unroll
            for (int r = 0; r < 4; r++) acc[mi][ni][r] = 0.f;

    float4 aReg[4], bReg[2];

    auto loadTile = [&](int kt) {
#pragma unroll
        for (int i = 0; i < 4; i++) {
            int idx = tid + i * 256;
            int row = idx >> 3, kc = (idx & 7) << 2;
            int grow = mBase + row;
            float4 v = make_float4(0.f, 0.f, 0.f, 0.f);
            if (grow < M)
                v = *reinterpret_cast<const float4*>(
                        &A[(size_t)grow * K + kt * GBK + kc]);
            aReg[i] = v;
        }
#pragma unroll
        for (int i = 0; i < 2; i++) {
            int idx = tid + i * 256;
            int kr = idx >> 4, nc = (idx & 15) << 2;
            bReg[i] = *reinterpret_cast<const float4*>(
                          &B[(size_t)(kt * GBK + kr) * N + nBase + nc]);
        }
    };
    auto stageTile = [&]() {
#pragma unroll
        for (int i = 0; i < 4; i++) {
            int idx = tid + i * 256;
            int row = idx >> 3, kc = (idx & 7) << 2;
            *reinterpret_cast<float4*>(&As[row][kc]) = aReg[i];
        }
#pragma unroll
        for (int i = 0; i < 2; i++) {
            int idx = tid + i * 256;
            int kr = idx >> 4, nc = (idx & 15) << 2;
            *reinterpret_cast<float4*>(&Bs[kr][nc]) = bReg[i];
        }
    };

    loadTile(0);
    stageTile();
    __syncthreads();

    for (int kt = 0; kt < KT; kt++) {
        if (kt + 1 < KT) loadTile(kt + 1);

#pragma unroll
        for (int ka = 0; ka < 4; ka++) {
            uint32_t ah[2][4], al[2][4], bh[4][2], bl[4][2];
#pragma unroll
            for (int mi = 0; mi < 2; mi++) {
                int row = warp_m * 32 + mi * 16 + g;
                int k0 = ka * 8 + tig;
                split_tf32(As[row][k0],       ah[mi][0], al[mi][0]);
                split_tf32(As[row + 8][k0],   ah[mi][1], al[mi][1]);
                split_tf32(As[row][k0 + 4],   ah[mi][2], al[mi][2]);
                split_tf32(As[row + 8][k0+4], ah[mi][3], al[mi][3]);
            }
#pragma unroll
            for (int ni = 0; ni < 4; ni++) {
                int col = warp_n * 32 + ni * 8 + g;
                split_tf32(Bs[ka * 8 + tig][col],     bh[ni][0], bl[ni][0]);
                split_tf32(Bs[ka * 8 + tig + 4][col], bh[ni][1], bl[ni][1]);
            }
#pragma unroll
            for (int mi = 0; mi < 2; mi++)
#pragma unroll
                for (int ni = 0; ni < 4; ni++) {
                    mma_tf32(acc[mi][ni], ah[mi], bh[ni]);
                    mma_tf32(acc[mi][ni], ah[mi], bl[ni]);
                    mma_tf32(acc[mi][ni], al[mi], bh[ni]);
                }
        }
        __syncthreads();
        if (kt + 1 < KT) {
            stageTile();
            __syncthreads();
        }
    }

    // store
#pragma unroll
    for (int mi = 0; mi < 2; mi++) {
        int row = mBase + warp_m * 32 + mi * 16 + g;
#pragma unroll
        for (int ni = 0; ni < 4; ni++) {
            int col = nBase + warp_n * 32 + ni * 8 + 2 * tig;
            if (HALF_OUT) {
                __half* C16 = (__half*)Cv;
                if (row < M)
                    *reinterpret_cast<__half2*>(&C16[(size_t)row * N + col]) =
                        __floats2half2_rn(acc[mi][ni][0], acc[mi][ni][1]);
                if (row + 8 < M)
                    *reinterpret_cast<__half2*>(&C16[(size_t)(row + 8) * N + col]) =
                        __floats2half2_rn(acc[mi][ni][2], acc[mi][ni][3]);
            } else {
                float* C = (float*)Cv;
                if (row < M)
                    *reinterpret_cast<float2*>(&C[(size_t)row * N + col]) =
                        make_float2(acc[mi][ni][0], acc[mi][ni][1]);
                if (row + 8 < M)
                    *reinterpret_cast<float2*>(&C[(size_t)(row + 8) * N + col]) =
                        make_float2(acc[mi][ni][2], acc[mi][ni][3]);
            }
        }
    }
}

// ---------------------------------------------------------------------------
// CSR SpMM, warp per node, fp16 gathers, fp32 accumulate, fused bias+ReLU.
// F=128: lane owns 4 features (uint2 = 2x half2 per gather, 2 wf/edge/warp).
// ---------------------------------------------------------------------------
__global__ __launch_bounds__(256) void spmm_f16_128(
    const float* __restrict__ vals, const int* __restrict__ cols,
    const int* __restrict__ rp, const uint2* __restrict__ Hv,
    const float4* __restrict__ bias4, float4* __restrict__ out4) {
    int node = blockIdx.x * 8 + (threadIdx.x >> 5);
    int lane = threadIdx.x & 31;
    if (node >= N_NODES) return;
    int s = rp[node], e = rp[node + 1];

    const uint2* __restrict__ Hl = Hv + lane;   // row stride 32 uint2

    float4 acc = make_float4(0.f, 0.f, 0.f, 0.f);

    auto accum = [&](int c, float v) {
        uint2 u = __ldg(&Hl[(size_t)c * 32]);
        float2 f0 = __half22float2(*reinterpret_cast<__half2*>(&u.x));
        float2 f1 = __half22float2(*reinterpret_cast<__half2*>(&u.y));
        acc.x = fmaf(v, f0.x, acc.x); acc.y = fmaf(v, f0.y, acc.y);
        acc.z = fmaf(v, f1.x, acc.z); acc.w = fmaf(v, f1.y, acc.w);
    };

    int i = s;
    for (; i < e && (i & 3); i++) accum(__ldg(&cols[i]), __ldg(&vals[i]));
    for (; i + 4 <= e; i += 4) {
        int4   c4 = __ldg(reinterpret_cast<const int4*>(&cols[i]));
        float4 v4 = __ldg(reinterpret_cast<const float4*>(&vals[i]));
        accum(c4.x, v4.x);
        accum(c4.y, v4.y);
        accum(c4.z, v4.z);
        accum(c4.w, v4.w);
    }
    for (; i < e; i++) accum(__ldg(&cols[i]), __ldg(&vals[i]));

    float4 b = bias4[lane];
    acc.x = fmaxf(acc.x + b.x, 0.f);
    acc.y = fmaxf(acc.y + b.y, 0.f);
    acc.z = fmaxf(acc.z + b.z, 0.f);
    acc.w = fmaxf(acc.w + b.w, 0.f);
    out4[(size_t)node * 32 + lane] = acc;
}

// F=64: lane owns 2 features (one half2 per gather, 1 wf/edge/warp).
__global__ __launch_bounds__(256) void spmm_f16_64(
    const float* __restrict__ vals, const int* __restrict__ cols,
    const int* __restrict__ rp, const uint32_t* __restrict__ Hv,
    const float2* __restrict__ bias2, float2* __restrict__ out2) {
    int node = blockIdx.x * 8 + (threadIdx.x >> 5);
    int lane = threadIdx.x & 31;
    if (node >= N_NODES) return;
    int s = rp[node], e = rp[node + 1];

    const uint32_t* __restrict__ Hl = Hv + lane;  // row stride 32 half2

    float2 acc = make_float2(0.f, 0.f);

    auto accum = [&](int c, float v) {
        uint32_t u = __ldg(&Hl[(size_t)c * 32]);
        float2 f = __half22float2(*reinterpret_cast<__half2*>(&u));
        acc.x = fmaf(v, f.x, acc.x);
        acc.y = fmaf(v, f.y, acc.y);
    };

    int i = s;
    for (; i < e && (i & 3); i++) accum(__ldg(&cols[i]), __ldg(&vals[i]));
    for (; i + 4 <= e; i += 4) {
        int4   c4 = __ldg(reinterpret_cast<const int4*>(&cols[i]));
        float4 v4 = __ldg(reinterpret_cast<const float4*>(&vals[i]));
        accum(c4.x, v4.x);
        accum(c4.y, v4.y);
        accum(c4.z, v4.z);
        accum(c4.w, v4.w);
    }
    for (; i < e; i++) accum(__ldg(&cols[i]), __ldg(&vals[i]));

    float2 b = bias2[lane];
    acc.x = fmaxf(acc.x + b.x, 0.f);
    acc.y = fmaxf(acc.y + b.y, 0.f);
    out2[(size_t)node * 32 + lane] = acc;
}

// ---------------------------------------------------------------------------
extern "C" void kernel_launch(void* const* d_in, const int* in_sizes, int n_in,
                              void* d_out, int out_size) {
    const float* x     = (const float*)d_in[0];
    const float* W1    = (const float*)d_in[1];
    const float* b1    = (const float*)d_in[2];
    const float* W2    = (const float*)d_in[3];
    const float* b2    = (const float*)d_in[4];
    const float* evals = (const float*)d_in[5];
    const int*   erows = (const int*)d_in[6];
    const int*   ecols = (const int*)d_in[7];
    float*       out   = (float*)d_out;

    const int E = in_sizes[5];

    void *pH0, *pH1, *pH2, *pRP;
    cudaGetSymbolAddress(&pH0, g_H0h);
    cudaGetSymbolAddress(&pH1, g_H1);
    cudaGetSymbolAddress(&pH2, g_H2h);
    cudaGetSymbolAddress(&pRP, g_rowptr);
    __half* H0h = (__half*)pH0;
    float*  H1  = (float*)pH1;
    __half* H2h = (__half*)pH2;
    int*    rp  = (int*)pRP;

    const int SPMM_GRID = (N_NODES + 7) / 8;

    // row_ptr from sorted rows
    rowptr_kernel<<<(N_NODES + 1 + 255) / 256, 256>>>(erows, E, rp);

    // GEMM1: H0h = fp16(x @ W1)   (M=100000, N=128, K=256)
    {
        dim3 grid((N_NODES + GBM - 1) / GBM, NHID / GBN);
        gemm_tf32_kernel<true><<<grid, 256>>>(x, W1, H0h, N_NODES, NHID, NFEAT);
    }

    // SpMM1: H1 = relu(A @ H0 + b1), single pass, fp16 gathers
    spmm_f16_128<<<SPMM_GRID, 256>>>(evals, ecols, rp, (const uint2*)H0h,
                                     (const float4*)b1, (float4*)H1);

    // GEMM2: H2h = fp16(H1 @ W2)   (M=100000, N=64, K=128)
    {
        dim3 grid((N_NODES + GBM - 1) / GBM, NHID2 / GBN);
        gemm_tf32_kernel<true><<<grid, 256>>>(H1, W2, H2h, N_NODES, NHID2, NHID);
    }

    // SpMM2: out = relu(A @ H2 + b2), fp16 gathers, fp32 out
    spmm_f16_64<<<SPMM_GRID, 256>>>(evals, ecols, rp, (const uint32_t*)H2h,
                                    (const float2*)b2, (float2*)out);
}